// round 7
// baseline (speedup 1.0000x reference)
#include <cuda_runtime.h>
#include <cuda_bf16.h>
#include <mma.h>
#include <cstdint>

using namespace nvcuda;

// ---------------------------------------------------------------------------
// GCN 2-layer forward. N=50000, d 128->128->64, E=800000 (+ implicit self loops)
// edge_index int32. tf32 tensor-core GEMMs; atomic-free CSR gather.
// GEMM1 overlapped with CSR build (stream fork). agg1+GEMM2 fused in one
// kernel: gather into smem, wmma from smem against L2-resident W2.
// ---------------------------------------------------------------------------

#define N_NODES 50000
#define M_PAD   50048
#define D_IN    128
#define D_HID   128
#define D_OUT   64
#define E_MAX   800000
#define NBLK    ((N_NODES + 255) / 256)   // 196

__device__ __align__(16) float g_dinv[N_NODES];
__device__ int   g_count[N_NODES];
__device__ int   g_rowptr[N_NODES + 1];
__device__ int   g_cursor[N_NODES];
__device__ int   g_bsum[NBLK];
__device__ __align__(16) int2 g_csr[E_MAX];        // {src, weight bits}
__device__ __align__(16) float g_H1[(size_t)M_PAD * D_HID];
__device__ __align__(16) float g_H2[(size_t)M_PAD * D_OUT];

// ---------------------------------------------------------------------------
// cp.async helpers
// ---------------------------------------------------------------------------
__device__ __forceinline__ void cp_async16(void* smem, const void* gmem, int srcbytes) {
    uint32_t s = (uint32_t)__cvta_generic_to_shared(smem);
    asm volatile("cp.async.cg.shared.global [%0], [%1], 16, %2;\n"
                 :: "r"(s), "l"(gmem), "r"(srcbytes));
}
__device__ __forceinline__ void cp_commit() {
    asm volatile("cp.async.commit_group;\n");
}
template <int N>
__device__ __forceinline__ void cp_wait() {
    asm volatile("cp.async.wait_group %0;\n" :: "n"(N));
}

// ---------------------------------------------------------------------------
// degree + dinv + CSR build
// ---------------------------------------------------------------------------
__global__ void k_deg_hist(const int* __restrict__ dst, int E) {
    int e = blockIdx.x * blockDim.x + threadIdx.x;
    if (e < E) atomicAdd(&g_count[dst[e]], 1);
}

__device__ __forceinline__ int warp_iscan(int x, int lane) {
    #pragma unroll
    for (int o = 1; o < 32; o <<= 1) {
        int y = __shfl_up_sync(0xffffffffu, x, o);
        if (lane >= o) x += y;
    }
    return x;
}

__global__ void k_scan1(int n) {
    int i = blockIdx.x * 256 + threadIdx.x;
    int lane = threadIdx.x & 31, w = threadIdx.x >> 5;
    int v = (i < n) ? g_count[i] : 0;
    if (i < n) g_dinv[i] = rsqrtf(1.0f + (float)v);   // +1 self loop
    int x = warp_iscan(v, lane);
    __shared__ int wsum[8];
    if (lane == 31) wsum[w] = x;
    __syncthreads();
    if (w == 0) {
        int s = (lane < 8) ? wsum[lane] : 0;
        #pragma unroll
        for (int o = 1; o < 8; o <<= 1) {
            int y = __shfl_up_sync(0xffffffffu, s, o);
            if (lane >= o) s += y;
        }
        if (lane < 8) wsum[lane] = s;
    }
    __syncthreads();
    int incl = x + ((w > 0) ? wsum[w - 1] : 0);
    if (i < n) g_rowptr[i] = incl - v;
    if (threadIdx.x == 255) g_bsum[blockIdx.x] = incl;
}

__global__ void k_scan2apply(int n, int E) {
    int t = threadIdx.x;
    int lane = t & 31, w = t >> 5;
    int v = (t < NBLK) ? g_bsum[t] : 0;
    int x = warp_iscan(v, lane);
    __shared__ int wsum[8];
    __shared__ int sb[256];
    if (lane == 31) wsum[w] = x;
    __syncthreads();
    if (w == 0) {
        int s = (lane < 8) ? wsum[lane] : 0;
        #pragma unroll
        for (int o = 1; o < 8; o <<= 1) {
            int y = __shfl_up_sync(0xffffffffu, s, o);
            if (lane >= o) s += y;
        }
        if (lane < 8) wsum[lane] = s;
    }
    __syncthreads();
    sb[t] = x + ((w > 0) ? wsum[w - 1] : 0) - v;
    __syncthreads();

    int i = blockIdx.x * 256 + t;
    if (i < n) {
        int r = g_rowptr[i] + sb[blockIdx.x];
        g_rowptr[i] = r;
        g_cursor[i] = r;
    }
    if (i == n) g_rowptr[n] = E;
}

__global__ void k_bin(const int* __restrict__ src,
                      const int* __restrict__ dst, int E) {
    int e = blockIdx.x * blockDim.x + threadIdx.x;
    if (e >= E) return;
    int s = src[e], d = dst[e];
    int pos = atomicAdd(&g_cursor[d], 1);
    g_csr[pos] = make_int2(s, __float_as_int(g_dinv[s]));
}

// ---------------------------------------------------------------------------
// tf32 tensor-core GEMM with cp.async 2-stage pipeline (used for GEMM1 only).
// ---------------------------------------------------------------------------
#define AS_LD 36
#define BS_LD 68
#define GEMM_SMEM (2 * (128 * AS_LD + 32 * BS_LD) * 4)

__global__ void __launch_bounds__(256)
k_gemm_tc(const float* __restrict__ A,
          const float* __restrict__ W,
          float* __restrict__ C,
          int M, int K, int N) {
    extern __shared__ __align__(16) float smem[];
    float (*As)[128][AS_LD] = reinterpret_cast<float (*)[128][AS_LD]>(smem);
    float (*Bs)[32][BS_LD]  = reinterpret_cast<float (*)[32][BS_LD]>(smem + 2 * 128 * AS_LD);

    const int tid = threadIdx.x;
    const int warp = tid >> 5;
    const int warp_m = warp & 3;
    const int warp_n = warp >> 2;
    const int row_base = blockIdx.y * 128;
    const int col_base = blockIdx.x * 64;

    const int a_r = tid >> 3;
    const int a_kv = tid & 7;
    const int b_kr = tid >> 4;
    const int b_cv = tid & 15;

    const int nchunks = K >> 5;

    auto load_chunk = [&](int c, int buf) {
        int k0 = c << 5;
        #pragma unroll
        for (int p = 0; p < 4; p++) {
            int r = p * 32 + a_r;
            int grow = row_base + r;
            int ok = (grow < M) ? 16 : 0;
            int ga = (grow < M) ? grow : (M - 1);
            cp_async16(&As[buf][r][a_kv * 4],
                       &A[(size_t)ga * K + k0 + a_kv * 4], ok);
        }
        #pragma unroll
        for (int p = 0; p < 2; p++) {
            int kr = p * 16 + b_kr;
            cp_async16(&Bs[buf][kr][b_cv * 4],
                       &W[(size_t)(k0 + kr) * N + col_base + b_cv * 4], 16);
        }
    };

    wmma::fragment<wmma::accumulator, 16, 16, 8, float> acc[2][2];
    #pragma unroll
    for (int i = 0; i < 2; i++)
        #pragma unroll
        for (int j = 0; j < 2; j++)
            wmma::fill_fragment(acc[i][j], 0.0f);

    load_chunk(0, 0);
    cp_commit();

    for (int c = 0; c < nchunks; c++) {
        if (c + 1 < nchunks) {
            load_chunk(c + 1, (c + 1) & 1);
            cp_commit();
            cp_wait<1>();
        } else {
            cp_wait<0>();
        }
        __syncthreads();

        int buf = c & 1;
        #pragma unroll
        for (int ks = 0; ks < 4; ks++) {
            wmma::fragment<wmma::matrix_a, 16, 16, 8, wmma::precision::tf32,
                           wmma::row_major> fa[2];
            wmma::fragment<wmma::matrix_b, 16, 16, 8, wmma::precision::tf32,
                           wmma::row_major> fb[2];
            #pragma unroll
            for (int i = 0; i < 2; i++) {
                wmma::load_matrix_sync(fa[i], &As[buf][warp_m * 32 + i * 16][ks * 8], AS_LD);
                #pragma unroll
                for (int t = 0; t < fa[i].num_elements; t++)
                    fa[i].x[t] = wmma::__float_to_tf32(fa[i].x[t]);
            }
            #pragma unroll
            for (int j = 0; j < 2; j++) {
                wmma::load_matrix_sync(fb[j], &Bs[buf][ks * 8][warp_n * 32 + j * 16], BS_LD);
                #pragma unroll
                for (int t = 0; t < fb[j].num_elements; t++)
                    fb[j].x[t] = wmma::__float_to_tf32(fb[j].x[t]);
            }
            #pragma unroll
            for (int i = 0; i < 2; i++)
                #pragma unroll
                for (int j = 0; j < 2; j++)
                    wmma::mma_sync(acc[i][j], fa[i], fb[j], acc[i][j]);
        }
        __syncthreads();
    }

    #pragma unroll
    for (int i = 0; i < 2; i++)
        #pragma unroll
        for (int j = 0; j < 2; j++) {
            int r = row_base + warp_m * 32 + i * 16;
            int c2 = col_base + warp_n * 32 + j * 16;
            wmma::store_matrix_sync(&C[(size_t)r * N + c2], acc[i][j], N,
                                    wmma::mem_row_major);
        }
}

// ---------------------------------------------------------------------------
// FUSED agg1 + GEMM2:
//   per block of 128 nodes:
//     Phase A: S[r][:] = relu(b1 + H1[r]*dinv^2 + sum_e H1[src]*w*dinv)  (smem)
//     Phase B: H2[block rows] = S @ W2   (tf32 wmma; W2 read from L2)
// 512 threads = 16 warps. Gather: warp handles 8 nodes, lane = float4 col.
// GEMM: 16 warps = 8(M) x 2(N), each 1x2 wmma 16x16x8 frags, K-loop 16.
// ---------------------------------------------------------------------------
#define FS_LD 136
#define FUSE_SMEM (128 * FS_LD * 4)

__global__ void __launch_bounds__(512)
k_agg_gemm(const float4* __restrict__ H,      // g_H1 as float4
           const float* __restrict__ b1,
           const float* __restrict__ W2,      // [128][64]
           float* __restrict__ C,             // g_H2 [M_PAD][64]
           int n) {
    extern __shared__ __align__(16) float S[];   // [128][FS_LD]

    const int tid = threadIdx.x;
    const int warp = tid >> 5;
    const int lane = tid & 31;
    const int row_base = blockIdx.x * 128;

    // ---- Phase A: gather 8 nodes per warp ----
    {
        float4 bb = *reinterpret_cast<const float4*>(&b1[lane * 4]);
        #pragma unroll
        for (int rr = 0; rr < 8; rr++) {
            int r = warp * 8 + rr;
            int node = row_base + r;
            float4 acc = make_float4(0.f, 0.f, 0.f, 0.f);
            if (node < n) {
                float dv = g_dinv[node];
                int beg = __ldg(&g_rowptr[node]);
                int end = __ldg(&g_rowptr[node + 1]);
                float4 h = __ldg(&H[(size_t)node * 32 + lane]);
                float self = dv * dv;
                acc = make_float4(h.x * self, h.y * self, h.z * self, h.w * self);
                if (beg < end) {
                    int2 cur = __ldg(&g_csr[beg]);
                    for (int e = beg; e < end; e++) {
                        int2 nxt = (e + 1 < end) ? __ldg(&g_csr[e + 1]) : cur;
                        float w = __int_as_float(cur.y) * dv;
                        float4 v = __ldg(&H[(size_t)cur.x * 32 + lane]);
                        acc.x = fmaf(v.x, w, acc.x);
                        acc.y = fmaf(v.y, w, acc.y);
                        acc.z = fmaf(v.z, w, acc.z);
                        acc.w = fmaf(v.w, w, acc.w);
                        cur = nxt;
                    }
                }
                acc.x = fmaxf(acc.x + bb.x, 0.f);
                acc.y = fmaxf(acc.y + bb.y, 0.f);
                acc.z = fmaxf(acc.z + bb.z, 0.f);
                acc.w = fmaxf(acc.w + bb.w, 0.f);
            }
            *reinterpret_cast<float4*>(&S[r * FS_LD + lane * 4]) = acc;
        }
    }
    __syncthreads();

    // ---- Phase B: C[128x64] = S[128x128] @ W2[128x64] ----
    {
        const int wm = warp & 7;        // M tile: rows wm*16..wm*16+15
        const int wn = warp >> 3;       // N half: cols wn*32..wn*32+31

        wmma::fragment<wmma::accumulator, 16, 16, 8, float> acc[2];
        wmma::fill_fragment(acc[0], 0.0f);
        wmma::fill_fragment(acc[1], 0.0f);

        #pragma unroll
        for (int kk = 0; kk < 16; kk++) {
            wmma::fragment<wmma::matrix_a, 16, 16, 8, wmma::precision::tf32,
                           wmma::row_major> fa;
            wmma::load_matrix_sync(fa, &S[(wm * 16) * FS_LD + kk * 8], FS_LD);
            #pragma unroll
            for (int t = 0; t < fa.num_elements; t++)
                fa.x[t] = wmma::__float_to_tf32(fa.x[t]);

            #pragma unroll
            for (int j = 0; j < 2; j++) {
                wmma::fragment<wmma::matrix_b, 16, 16, 8, wmma::precision::tf32,
                               wmma::row_major> fb;
                wmma::load_matrix_sync(fb, &W2[(size_t)(kk * 8) * D_OUT + wn * 32 + j * 16],
                                       D_OUT);
                #pragma unroll
                for (int t = 0; t < fb.num_elements; t++)
                    fb.x[t] = wmma::__float_to_tf32(fb.x[t]);
                wmma::mma_sync(acc[j], fa, fb, acc[j]);
            }
        }

        #pragma unroll
        for (int j = 0; j < 2; j++) {
            int r = row_base + wm * 16;
            int c = wn * 32 + j * 16;
            wmma::store_matrix_sync(&C[(size_t)r * D_OUT + c], acc[j], D_OUT,
                                    wmma::mem_row_major);
        }
    }
}

// ---------------------------------------------------------------------------
// agg2 (final layer): out = agg(H2)*norm + b2. TPN=16 lanes per node.
// ---------------------------------------------------------------------------
template <int TPN, bool RELU>
__global__ void k_agg(const float4* __restrict__ H,
                      const float* __restrict__ bias,
                      float4* __restrict__ out, int n) {
    int t = blockIdx.x * blockDim.x + threadIdx.x;
    int node = t / TPN;
    int q = t % TPN;
    if (node >= n) return;

    float dv = g_dinv[node];
    int beg = __ldg(&g_rowptr[node]);
    int end = __ldg(&g_rowptr[node + 1]);

    float4 h = __ldg(&H[(size_t)node * TPN + q]);
    float self = dv * dv;
    float4 acc = make_float4(h.x * self, h.y * self, h.z * self, h.w * self);

    if (beg < end) {
        int2 cur = __ldg(&g_csr[beg]);
        for (int e = beg; e < end; e++) {
            int2 nxt = (e + 1 < end) ? __ldg(&g_csr[e + 1]) : cur;
            float w = __int_as_float(cur.y) * dv;
            float4 v = __ldg(&H[(size_t)cur.x * TPN + q]);
            acc.x = fmaf(v.x, w, acc.x);
            acc.y = fmaf(v.y, w, acc.y);
            acc.z = fmaf(v.z, w, acc.z);
            acc.w = fmaf(v.w, w, acc.w);
            cur = nxt;
        }
    }
    float4 bb = *reinterpret_cast<const float4*>(&bias[q * 4]);
    acc.x += bb.x; acc.y += bb.y; acc.z += bb.z; acc.w += bb.w;
    if (RELU) {
        acc.x = fmaxf(acc.x, 0.f); acc.y = fmaxf(acc.y, 0.f);
        acc.z = fmaxf(acc.z, 0.f); acc.w = fmaxf(acc.w, 0.f);
    }
    out[(size_t)node * TPN + q] = acc;
}

// ---------------------------------------------------------------------------
// launch
// ---------------------------------------------------------------------------
extern "C" void kernel_launch(void* const* d_in, const int* in_sizes, int n_in,
                              void* d_out, int out_size) {
    const float* x   = (const float*)d_in[0];
    const int*   ei  = (const int*)d_in[1];    // int32 (JAX x64 disabled)
    const float* W1  = (const float*)d_in[2];
    const float* b1  = (const float*)d_in[3];
    const float* W2  = (const float*)d_in[4];
    const float* b2  = (const float*)d_in[5];
    float*       out = (float*)d_out;

    const int n = in_sizes[0] / D_IN;       // 50000
    const int E = in_sizes[1] / 2;          // 800000
    const int* srcs = ei;
    const int* dsts = ei + E;

    float* H1 = nullptr; float* H2 = nullptr; int* cnt = nullptr;
    cudaGetSymbolAddress((void**)&H1,  g_H1);
    cudaGetSymbolAddress((void**)&H2,  g_H2);
    cudaGetSymbolAddress((void**)&cnt, g_count);

    static cudaStream_t s1 = nullptr;
    static cudaEvent_t  evFork = nullptr, evJoin = nullptr;
    if (!s1) {
        cudaFuncSetAttribute(k_gemm_tc,
                             cudaFuncAttributeMaxDynamicSharedMemorySize, GEMM_SMEM);
        cudaFuncSetAttribute(k_agg_gemm,
                             cudaFuncAttributeMaxDynamicSharedMemorySize, FUSE_SMEM);
        cudaStreamCreateWithFlags(&s1, cudaStreamNonBlocking);
        cudaEventCreateWithFlags(&evFork, cudaEventDisableTiming);
        cudaEventCreateWithFlags(&evJoin, cudaEventDisableTiming);
    }

    const int T = 256;
    const int nb = (n + T - 1) / T;         // 196
    const int mblocks = (n + 127) / 128;    // 391

    // ---- fork: GEMM1 on s1, concurrent with CSR build on stream 0 ----
    cudaEventRecord(evFork, 0);
    cudaStreamWaitEvent(s1, evFork, 0);
    {
        dim3 grid(D_HID / 64, mblocks);
        k_gemm_tc<<<grid, 256, GEMM_SMEM, s1>>>(x, W1, H1, n, D_IN, D_HID);
    }
    cudaEventRecord(evJoin, s1);

    // ---- CSR build on capture stream ----
    cudaMemsetAsync(cnt, 0, (size_t)n * sizeof(int));
    k_deg_hist<<<(E + T - 1) / T, T>>>(dsts, E);
    k_scan1<<<nb, T>>>(n);
    k_scan2apply<<<nb, T>>>(n, E);
    k_bin<<<(E + T - 1) / T, T>>>(srcs, dsts, E);

    // ---- join: fused kernel needs both H1 and CSR ----
    cudaStreamWaitEvent(0, evJoin, 0);

    // fused agg1 + GEMM2 -> H2
    k_agg_gemm<<<mblocks, 512, FUSE_SMEM>>>(
        (const float4*)H1, b1, W2, H2, n);

    // aggregation layer 2: out = agg(H2) + b2
    {
        long long work = (long long)n * (D_OUT / 4);
        k_agg<D_OUT / 4, false><<<(int)((work + T - 1) / T), T>>>(
            (const float4*)H2, b2, (float4*)out, n);
    }
}

// round 8
// speedup vs baseline: 1.0513x; 1.0513x over previous
#include <cuda_runtime.h>
#include <cuda_fp16.h>
#include <mma.h>
#include <cstdint>

using namespace nvcuda;

// ---------------------------------------------------------------------------
// GCN 2-layer forward. N=50000, d 128->128->64, E=800000 (+ implicit self loops)
// edge_index int32. tf32 tensor-core GEMMs (cp.async pipeline); atomic-free
// CSR gather aggregation (H1 in fp16 to halve gather traffic).
// CSR build overlapped with GEMM1 via stream fork. ILP-4 hist/bin.
// ---------------------------------------------------------------------------

#define N_NODES 50000
#define M_PAD   50048
#define D_IN    128
#define D_HID   128
#define D_OUT   64
#define E_MAX   800000
#define NBLK    ((N_NODES + 255) / 256)   // 196

__device__ __align__(16) float g_dinv[N_NODES];
__device__ int   g_count[N_NODES];
__device__ int   g_rowptr[N_NODES + 1];
__device__ int   g_cursor[N_NODES];
__device__ int   g_bsum[NBLK];
__device__ __align__(16) int2   g_csr[E_MAX];      // {src, weight bits}
__device__ __align__(16) __half g_H1[(size_t)M_PAD * D_HID];   // fp16!
__device__ __align__(16) float  g_OUT1[(size_t)M_PAD * D_HID];
__device__ __align__(16) float  g_H2[(size_t)M_PAD * D_OUT];

// ---------------------------------------------------------------------------
// cp.async helpers
// ---------------------------------------------------------------------------
__device__ __forceinline__ void cp_async16(void* smem, const void* gmem, int srcbytes) {
    uint32_t s = (uint32_t)__cvta_generic_to_shared(smem);
    asm volatile("cp.async.cg.shared.global [%0], [%1], 16, %2;\n"
                 :: "r"(s), "l"(gmem), "r"(srcbytes));
}
__device__ __forceinline__ void cp_commit() {
    asm volatile("cp.async.commit_group;\n");
}
template <int N>
__device__ __forceinline__ void cp_wait() {
    asm volatile("cp.async.wait_group %0;\n" :: "n"(N));
}

// ---------------------------------------------------------------------------
// degree + dinv + CSR build
// ---------------------------------------------------------------------------
__global__ void k_deg_hist4(const int4* __restrict__ dst4, int E4, int E) {
    int t = blockIdx.x * blockDim.x + threadIdx.x;
    if (t < E4) {
        int4 d = __ldg(&dst4[t]);
        atomicAdd(&g_count[d.x], 1);
        atomicAdd(&g_count[d.y], 1);
        atomicAdd(&g_count[d.z], 1);
        atomicAdd(&g_count[d.w], 1);
    }
    if (t == 0) {
        const int* d = (const int*)dst4;
        for (int e = E4 * 4; e < E; e++) atomicAdd(&g_count[d[e]], 1);
    }
}

__device__ __forceinline__ int warp_iscan(int x, int lane) {
    #pragma unroll
    for (int o = 1; o < 32; o <<= 1) {
        int y = __shfl_up_sync(0xffffffffu, x, o);
        if (lane >= o) x += y;
    }
    return x;
}

__global__ void k_scan1(int n) {
    int i = blockIdx.x * 256 + threadIdx.x;
    int lane = threadIdx.x & 31, w = threadIdx.x >> 5;
    int v = (i < n) ? g_count[i] : 0;
    if (i < n) g_dinv[i] = rsqrtf(1.0f + (float)v);   // +1 self loop
    int x = warp_iscan(v, lane);
    __shared__ int wsum[8];
    if (lane == 31) wsum[w] = x;
    __syncthreads();
    if (w == 0) {
        int s = (lane < 8) ? wsum[lane] : 0;
        #pragma unroll
        for (int o = 1; o < 8; o <<= 1) {
            int y = __shfl_up_sync(0xffffffffu, s, o);
            if (lane >= o) s += y;
        }
        if (lane < 8) wsum[lane] = s;
    }
    __syncthreads();
    int incl = x + ((w > 0) ? wsum[w - 1] : 0);
    if (i < n) g_rowptr[i] = incl - v;
    if (threadIdx.x == 255) g_bsum[blockIdx.x] = incl;
}

__global__ void k_scan2apply(int n, int E) {
    int t = threadIdx.x;
    int lane = t & 31, w = t >> 5;
    int v = (t < NBLK) ? g_bsum[t] : 0;
    int x = warp_iscan(v, lane);
    __shared__ int wsum[8];
    __shared__ int sb[256];
    if (lane == 31) wsum[w] = x;
    __syncthreads();
    if (w == 0) {
        int s = (lane < 8) ? wsum[lane] : 0;
        #pragma unroll
        for (int o = 1; o < 8; o <<= 1) {
            int y = __shfl_up_sync(0xffffffffu, s, o);
            if (lane >= o) s += y;
        }
        if (lane < 8) wsum[lane] = s;
    }
    __syncthreads();
    sb[t] = x + ((w > 0) ? wsum[w - 1] : 0) - v;
    __syncthreads();

    int i = blockIdx.x * 256 + t;
    if (i < n) {
        int r = g_rowptr[i] + sb[blockIdx.x];
        g_rowptr[i] = r;
        g_cursor[i] = r;
    }
    if (i == n) g_rowptr[n] = E;
}

__global__ void k_bin4(const int4* __restrict__ src4,
                       const int4* __restrict__ dst4, int E4, int E) {
    int t = blockIdx.x * blockDim.x + threadIdx.x;
    if (t < E4) {
        int4 s = __ldg(&src4[t]);
        int4 d = __ldg(&dst4[t]);
        int p0 = atomicAdd(&g_cursor[d.x], 1);
        int p1 = atomicAdd(&g_cursor[d.y], 1);
        int p2 = atomicAdd(&g_cursor[d.z], 1);
        int p3 = atomicAdd(&g_cursor[d.w], 1);
        g_csr[p0] = make_int2(s.x, __float_as_int(g_dinv[s.x]));
        g_csr[p1] = make_int2(s.y, __float_as_int(g_dinv[s.y]));
        g_csr[p2] = make_int2(s.z, __float_as_int(g_dinv[s.z]));
        g_csr[p3] = make_int2(s.w, __float_as_int(g_dinv[s.w]));
    }
    if (t == 0) {
        const int* s = (const int*)src4;
        const int* d = (const int*)dst4;
        for (int e = E4 * 4; e < E; e++) {
            int pos = atomicAdd(&g_cursor[d[e]], 1);
            g_csr[pos] = make_int2(s[e], __float_as_int(g_dinv[s[e]]));
        }
    }
}

// ---------------------------------------------------------------------------
// tf32 tensor-core GEMM, cp.async 2-stage pipeline, 128x64 tile, 8 warps.
// HALF_OUT: convert C tile to fp16 via smem staging before the global store.
// ---------------------------------------------------------------------------
#define AS_LD 36
#define BS_LD 68
#define GEMM_SMEM (2 * (128 * AS_LD + 32 * BS_LD) * 4)
#define ST_LD 68

template <bool HALF_OUT>
__global__ void __launch_bounds__(256)
k_gemm_tc(const float* __restrict__ A,
          const float* __restrict__ W,
          void* __restrict__ Cv,
          int M, int K, int N) {
    extern __shared__ __align__(16) float smem[];
    float (*As)[128][AS_LD] = reinterpret_cast<float (*)[128][AS_LD]>(smem);
    float (*Bs)[32][BS_LD]  = reinterpret_cast<float (*)[32][BS_LD]>(smem + 2 * 128 * AS_LD);

    const int tid = threadIdx.x;
    const int warp = tid >> 5;
    const int warp_m = warp & 3;
    const int warp_n = warp >> 2;
    const int row_base = blockIdx.y * 128;
    const int col_base = blockIdx.x * 64;

    const int a_r = tid >> 3;
    const int a_kv = tid & 7;
    const int b_kr = tid >> 4;
    const int b_cv = tid & 15;

    const int nchunks = K >> 5;

    auto load_chunk = [&](int c, int buf) {
        int k0 = c << 5;
        #pragma unroll
        for (int p = 0; p < 4; p++) {
            int r = p * 32 + a_r;
            int grow = row_base + r;
            int ok = (grow < M) ? 16 : 0;
            int ga = (grow < M) ? grow : (M - 1);
            cp_async16(&As[buf][r][a_kv * 4],
                       &A[(size_t)ga * K + k0 + a_kv * 4], ok);
        }
        #pragma unroll
        for (int p = 0; p < 2; p++) {
            int kr = p * 16 + b_kr;
            cp_async16(&Bs[buf][kr][b_cv * 4],
                       &W[(size_t)(k0 + kr) * N + col_base + b_cv * 4], 16);
        }
    };

    wmma::fragment<wmma::accumulator, 16, 16, 8, float> acc[2][2];
    #pragma unroll
    for (int i = 0; i < 2; i++)
        #pragma unroll
        for (int j = 0; j < 2; j++)
            wmma::fill_fragment(acc[i][j], 0.0f);

    load_chunk(0, 0);
    cp_commit();

    for (int c = 0; c < nchunks; c++) {
        if (c + 1 < nchunks) {
            load_chunk(c + 1, (c + 1) & 1);
            cp_commit();
            cp_wait<1>();
        } else {
            cp_wait<0>();
        }
        __syncthreads();

        int buf = c & 1;
        #pragma unroll
        for (int ks = 0; ks < 4; ks++) {
            wmma::fragment<wmma::matrix_a, 16, 16, 8, wmma::precision::tf32,
                           wmma::row_major> fa[2];
            wmma::fragment<wmma::matrix_b, 16, 16, 8, wmma::precision::tf32,
                           wmma::row_major> fb[2];
            #pragma unroll
            for (int i = 0; i < 2; i++) {
                wmma::load_matrix_sync(fa[i], &As[buf][warp_m * 32 + i * 16][ks * 8], AS_LD);
                #pragma unroll
                for (int t = 0; t < fa[i].num_elements; t++)
                    fa[i].x[t] = wmma::__float_to_tf32(fa[i].x[t]);
            }
            #pragma unroll
            for (int j = 0; j < 2; j++) {
                wmma::load_matrix_sync(fb[j], &Bs[buf][ks * 8][warp_n * 32 + j * 16], BS_LD);
                #pragma unroll
                for (int t = 0; t < fb[j].num_elements; t++)
                    fb[j].x[t] = wmma::__float_to_tf32(fb[j].x[t]);
            }
            #pragma unroll
            for (int i = 0; i < 2; i++)
                #pragma unroll
                for (int j = 0; j < 2; j++)
                    wmma::mma_sync(acc[i][j], fa[i], fb[j], acc[i][j]);
        }
        __syncthreads();
    }

    if (!HALF_OUT) {
        float* C = (float*)Cv;
        #pragma unroll
        for (int i = 0; i < 2; i++)
            #pragma unroll
            for (int j = 0; j < 2; j++) {
                int r = row_base + warp_m * 32 + i * 16;
                int c2 = col_base + warp_n * 32 + j * 16;
                wmma::store_matrix_sync(&C[(size_t)r * N + c2], acc[i][j], N,
                                        wmma::mem_row_major);
            }
    } else {
        // stage fp32 tile in smem, convert to fp16, write half2
        float* St = smem;   // reuse: 128 x ST_LD floats = 34.8KB <= GEMM_SMEM
        #pragma unroll
        for (int i = 0; i < 2; i++)
            #pragma unroll
            for (int j = 0; j < 2; j++) {
                int r = warp_m * 32 + i * 16;
                int c2 = warp_n * 32 + j * 16;
                wmma::store_matrix_sync(&St[(size_t)r * ST_LD + c2], acc[i][j], ST_LD,
                                        wmma::mem_row_major);
            }
        __syncthreads();
        __half* C = (__half*)Cv;
        int r = tid >> 1;                 // 0..127
        int half = tid & 1;               // col group of 32
        const float* row = &St[(size_t)r * ST_LD + half * 32];
        __half2* dst = reinterpret_cast<__half2*>(
            &C[(size_t)(row_base + r) * N + col_base + half * 32]);
        #pragma unroll
        for (int j = 0; j < 16; j++) {
            float2 f = make_float2(row[2 * j], row[2 * j + 1]);
            dst[j] = __float22half2_rn(f);
        }
    }
}

// ---------------------------------------------------------------------------
// agg1 on fp16 H1: TPN=16 lanes per node, each lane owns 8 halves (uint4).
//   OUT1 = relu(b1 + H1[i]*dinv^2 + sum_e H1[src]*w*dinv)   (fp32 out)
// ---------------------------------------------------------------------------
__device__ __forceinline__ void h8_fma(float* acc, uint4 v, float w) {
    const __half2* p = reinterpret_cast<const __half2*>(&v);
    #pragma unroll
    for (int i = 0; i < 4; i++) {
        float2 f = __half22float2(p[i]);
        acc[2 * i]     = fmaf(f.x, w, acc[2 * i]);
        acc[2 * i + 1] = fmaf(f.y, w, acc[2 * i + 1]);
    }
}

__global__ void k_agg1_h(const uint4* __restrict__ Hh,   // g_H1 as uint4 (8 halves)
                         const float* __restrict__ b1,
                         float4* __restrict__ OUT1, int n) {
    int t = blockIdx.x * blockDim.x + threadIdx.x;
    int node = t >> 4;           // /16
    int q = t & 15;
    if (node >= n) return;

    float dv = g_dinv[node];
    int beg = __ldg(&g_rowptr[node]);
    int end = __ldg(&g_rowptr[node + 1]);

    float acc[8] = {};
    uint4 hv = __ldg(&Hh[(size_t)node * 16 + q]);
    h8_fma(acc, hv, dv * dv);

    if (beg < end) {
        int2 cur = __ldg(&g_csr[beg]);
        for (int e = beg; e < end; e++) {
            int2 nxt = (e + 1 < end) ? __ldg(&g_csr[e + 1]) : cur;
            float w = __int_as_float(cur.y) * dv;
            uint4 v = __ldg(&Hh[(size_t)cur.x * 16 + q]);
            h8_fma(acc, v, w);
            cur = nxt;
        }
    }
    float4 b0 = *reinterpret_cast<const float4*>(&b1[q * 8]);
    float4 b1v = *reinterpret_cast<const float4*>(&b1[q * 8 + 4]);
    float4 o0 = make_float4(fmaxf(acc[0] + b0.x, 0.f), fmaxf(acc[1] + b0.y, 0.f),
                            fmaxf(acc[2] + b0.z, 0.f), fmaxf(acc[3] + b0.w, 0.f));
    float4 o1 = make_float4(fmaxf(acc[4] + b1v.x, 0.f), fmaxf(acc[5] + b1v.y, 0.f),
                            fmaxf(acc[6] + b1v.z, 0.f), fmaxf(acc[7] + b1v.w, 0.f));
    OUT1[(size_t)node * 32 + q * 2]     = o0;
    OUT1[(size_t)node * 32 + q * 2 + 1] = o1;
}

// ---------------------------------------------------------------------------
// agg2 (fp32 H2): TPN=16 lanes per node, one float4 each. out = agg + b2.
// ---------------------------------------------------------------------------
__global__ void k_agg2(const float4* __restrict__ H,
                       const float* __restrict__ bias,
                       float4* __restrict__ out, int n) {
    const int TPN = 16;
    int t = blockIdx.x * blockDim.x + threadIdx.x;
    int node = t / TPN;
    int q = t % TPN;
    if (node >= n) return;

    float dv = g_dinv[node];
    int beg = __ldg(&g_rowptr[node]);
    int end = __ldg(&g_rowptr[node + 1]);

    float4 h = __ldg(&H[(size_t)node * TPN + q]);
    float self = dv * dv;
    float4 acc = make_float4(h.x * self, h.y * self, h.z * self, h.w * self);

    if (beg < end) {
        int2 cur = __ldg(&g_csr[beg]);
        for (int e = beg; e < end; e++) {
            int2 nxt = (e + 1 < end) ? __ldg(&g_csr[e + 1]) : cur;
            float w = __int_as_float(cur.y) * dv;
            float4 v = __ldg(&H[(size_t)cur.x * TPN + q]);
            acc.x = fmaf(v.x, w, acc.x);
            acc.y = fmaf(v.y, w, acc.y);
            acc.z = fmaf(v.z, w, acc.z);
            acc.w = fmaf(v.w, w, acc.w);
            cur = nxt;
        }
    }
    float4 bb = *reinterpret_cast<const float4*>(&bias[q * 4]);
    acc.x += bb.x; acc.y += bb.y; acc.z += bb.z; acc.w += bb.w;
    out[(size_t)node * TPN + q] = acc;
}

// ---------------------------------------------------------------------------
// launch: CSR build on capture stream, GEMM1 forked onto side stream.
// ---------------------------------------------------------------------------
extern "C" void kernel_launch(void* const* d_in, const int* in_sizes, int n_in,
                              void* d_out, int out_size) {
    const float* x   = (const float*)d_in[0];
    const int*   ei  = (const int*)d_in[1];    // int32 (JAX x64 disabled)
    const float* W1  = (const float*)d_in[2];
    const float* b1  = (const float*)d_in[3];
    const float* W2  = (const float*)d_in[4];
    const float* b2  = (const float*)d_in[5];
    float*       out = (float*)d_out;

    const int n = in_sizes[0] / D_IN;       // 50000
    const int E = in_sizes[1] / 2;          // 800000
    const int* srcs = ei;
    const int* dsts = ei + E;
    const int E4 = E >> 2;

    __half* H1 = nullptr; float* OUT1 = nullptr; float* H2 = nullptr;
    int* cnt = nullptr;
    cudaGetSymbolAddress((void**)&H1,   g_H1);
    cudaGetSymbolAddress((void**)&OUT1, g_OUT1);
    cudaGetSymbolAddress((void**)&H2,   g_H2);
    cudaGetSymbolAddress((void**)&cnt,  g_count);

    static cudaStream_t s1 = nullptr;
    static cudaEvent_t  evFork = nullptr, evJoin = nullptr;
    if (!s1) {
        cudaFuncSetAttribute(k_gemm_tc<false>,
                             cudaFuncAttributeMaxDynamicSharedMemorySize, GEMM_SMEM);
        cudaFuncSetAttribute(k_gemm_tc<true>,
                             cudaFuncAttributeMaxDynamicSharedMemorySize, GEMM_SMEM);
        cudaStreamCreateWithFlags(&s1, cudaStreamNonBlocking);
        cudaEventCreateWithFlags(&evFork, cudaEventDisableTiming);
        cudaEventCreateWithFlags(&evJoin, cudaEventDisableTiming);
    }

    const int T = 256;
    const int nb = (n + T - 1) / T;         // 196
    const int mblocks = (n + 127) / 128;    // 391

    // ---- fork: GEMM1 (fp16 out) on s1, concurrent with CSR build ----
    cudaEventRecord(evFork, 0);
    cudaStreamWaitEvent(s1, evFork, 0);
    {
        dim3 grid(D_HID / 64, mblocks);
        k_gemm_tc<true><<<grid, 256, GEMM_SMEM, s1>>>(x, W1, H1, n, D_IN, D_HID);
    }
    cudaEventRecord(evJoin, s1);

    // ---- CSR build on capture stream ----
    cudaMemsetAsync(cnt, 0, (size_t)n * sizeof(int));
    k_deg_hist4<<<(E4 + T - 1) / T, T>>>((const int4*)dsts, E4, E);
    k_scan1<<<nb, T>>>(n);
    k_scan2apply<<<nb, T>>>(n, E);
    k_bin4<<<(E4 + T - 1) / T, T>>>((const int4*)srcs, (const int4*)dsts, E4, E);

    // ---- join ----
    cudaStreamWaitEvent(0, evJoin, 0);

    // agg1 (fp16 gather): OUT1 = relu(agg(H1) + b1)
    {
        long long work = (long long)n * 16;
        k_agg1_h<<<(int)((work + T - 1) / T), T>>>(
            (const uint4*)H1, b1, (float4*)OUT1, n);
    }

    // GEMM2: H2 = OUT1 @ W2 (fp32 out)
    {
        dim3 grid(D_OUT / 64, mblocks);
        k_gemm_tc<false><<<grid, 256, GEMM_SMEM>>>(OUT1, W2, H2, n, D_HID, D_OUT);
    }

    // agg2: out = agg(H2) + b2
    {
        long long work = (long long)n * 16;
        k_agg2<<<(int)((work + T - 1) / T), T>>>(
            (const float4*)H2, b2, (float4*)out, n);
    }
}